// round 16
// baseline (speedup 1.0000x reference)
#include <cuda_runtime.h>
#include <cuda_bf16.h>

#define NN 8192
#define IN_N 1024
#define OUT_N 256

#define S_FULL 64            // row splits for full gemv  (128 rows each)
#define S_IN   64            // row splits for input gemv (16 rows each)
#define S_OUT  256           // row splits for last-cols gemv (32 rows each)
#define TAIL_START 76        // step-2 rows >= this (per split) pinned evict_last (~106 MB)

// scratch (no allocation allowed): three s vectors, zeroed each call
__device__ float g_s[3][NN];

// ---------------------------------------------------------------------------
// 32-byte (8-float) L2 eviction-priority loads: ptxas requires .v4.b64 form
// for L2::evict_* vector loads on sm_103.
// ---------------------------------------------------------------------------
struct f8 { float v[8]; };

__device__ __forceinline__ f8 ldg8_evict_last(const float* p) {
    unsigned long long x0, x1, x2, x3;
    asm volatile("ld.global.nc.L2::evict_last.v4.b64 {%0,%1,%2,%3}, [%4];"
                 : "=l"(x0), "=l"(x1), "=l"(x2), "=l"(x3) : "l"(p));
    f8 r;
    *reinterpret_cast<unsigned long long*>(&r.v[0]) = x0;
    *reinterpret_cast<unsigned long long*>(&r.v[2]) = x1;
    *reinterpret_cast<unsigned long long*>(&r.v[4]) = x2;
    *reinterpret_cast<unsigned long long*>(&r.v[6]) = x3;
    return r;
}
__device__ __forceinline__ f8 ldg8_evict_first(const float* p) {
    unsigned long long x0, x1, x2, x3;
    asm volatile("ld.global.nc.L2::evict_first.v4.b64 {%0,%1,%2,%3}, [%4];"
                 : "=l"(x0), "=l"(x1), "=l"(x2), "=l"(x3) : "l"(p));
    f8 r;
    *reinterpret_cast<unsigned long long*>(&r.v[0]) = x0;
    *reinterpret_cast<unsigned long long*>(&r.v[2]) = x1;
    *reinterpret_cast<unsigned long long*>(&r.v[4]) = x2;
    *reinterpret_cast<unsigned long long*>(&r.v[6]) = x3;
    return r;
}

// ---------------------------------------------------------------------------
// zero the accumulator vectors and the output
// ---------------------------------------------------------------------------
__global__ __launch_bounds__(256) void zero_accum(float* __restrict__ s,
                                                  float* __restrict__ out)
{
    const int i = blockIdx.x * blockDim.x + threadIdx.x;
    if (i < 3 * NN) s[i] = 0.f;
    if (i < OUT_N)  out[i] = 0.f;
}

// ---------------------------------------------------------------------------
// s_out[j] += sum_i W[i, j] * v[i]  over rows [split*rps, split*rps+rps)
// thread owns 8 consecutive columns (one 32B load/row), register accum,
// 8 spread-address atomicAdds (REDG) at the end.
//
// MODE 0 (step 1): ascending, all rows evict_last   (32 MB, reused by step 2)
// MODE 1 (step 2): ascending, rows < TAIL_START evict_first, rest evict_last
//                  (pins ~106 MB tail for step 3)
// MODE 2 (step 3): DESCENDING, all evict_first (consume pinned tail first,
//                  stream head misses without churning it)
// grid: (NN/2048, n_splits) = (4, n_splits), block: 256
// ---------------------------------------------------------------------------
template <int MODE>
__global__ __launch_bounds__(256) void gemvT_atomic(
    const float* __restrict__ W, const float* __restrict__ v,
    float* __restrict__ s_out, int rows_per_split)
{
    const int split = blockIdx.y;
    const int c8 = blockIdx.x * blockDim.x + threadIdx.x;   // float8 column index
    const int r0 = split * rows_per_split;

    float acc[8];
#pragma unroll
    for (int k = 0; k < 8; k++) acc[k] = 0.f;

    for (int i = 0; i < rows_per_split; i += 4) {
        const int ib = (MODE == 2) ? (rows_per_split - 4 - i) : i;
#pragma unroll
        for (int u = 0; u < 4; u++) {
            const int ri = ib + u;              // row within split
            const int r  = r0 + ri;
            const float sv = __ldg(&v[r]);
            const float* wp = W + (size_t)r * NN + 8 * c8;
            f8 w;
            if (MODE == 0)      w = ldg8_evict_last(wp);
            else if (MODE == 1) w = (ri >= TAIL_START) ? ldg8_evict_last(wp)
                                                       : ldg8_evict_first(wp);
            else                w = ldg8_evict_first(wp);
#pragma unroll
            for (int k = 0; k < 8; k++)
                acc[k] = fmaf(w.v[k], sv, acc[k]);
        }
    }

    float* dst = s_out + 8 * c8;
#pragma unroll
    for (int k = 0; k < 8; k++)
        atomicAdd(dst + k, acc[k]);
}

// ---------------------------------------------------------------------------
// last-256-columns gemv fused with diagonal scale:
//   out[j] += W[d,d] * sum_{i in split} W[i, NN-256+j] * v[i],  d = NN-256+j
// ---------------------------------------------------------------------------
__global__ __launch_bounds__(256) void gemvT_lastcols_atomic(
    const float* __restrict__ W, const float* __restrict__ v,
    float* __restrict__ out, int rows_per_split)
{
    const int split = blockIdx.x;
    const int j = threadIdx.x;                 // 0..255
    const int colg = NN - OUT_N + j;
    const int r0 = split * rows_per_split;

    float acc = 0.f;
#pragma unroll 4
    for (int i = 0; i < rows_per_split; i++) {
        const int r = r0 + i;
        acc = fmaf(__ldg(&W[(size_t)r * NN + colg]), __ldg(&v[r]), acc);
    }

    const float wdd = __ldg(&W[(size_t)colg * NN + colg]);
    atomicAdd(&out[j], wdd * acc);
}

extern "C" void kernel_launch(void* const* d_in, const int* in_sizes, int n_in,
                              void* d_out, int out_size)
{
    // identify inputs by size (robust to ordering): x=1024, W=8192*8192
    const float* x = nullptr;
    const float* W = nullptr;
    for (int i = 0; i < n_in; i++) {
        if (in_sizes[i] == IN_N) x = (const float*)d_in[i];
        else if (in_sizes[i] == NN * NN) W = (const float*)d_in[i];
    }
    if (!x) x = (const float*)d_in[0];
    if (!W) W = (const float*)d_in[1];
    float* out = (float*)d_out;

    float* sbase; cudaGetSymbolAddress((void**)&sbase, g_s);
    float* s1 = sbase;            // g_s[0]
    float* s2 = sbase + NN;       // g_s[1]
    float* s3 = sbase + 2 * NN;   // g_s[2]

    const dim3 blk(256);

    // zero accumulators + out (must precede all atomics; stream serializes)
    zero_accum<<<(3 * NN + 255) / 256, blk>>>(sbase, out);

    // step 1: s1 = W[0:1024,:]^T x  -- 32 MB, evict_last (step 2 re-reads it)
    gemvT_atomic<0><<<dim3(NN / 2048, S_IN), blk>>>(W, x, s1, IN_N / S_IN);

    // step 2: s2 = W^T s1 (full 268 MB) ascending; tail rows pinned evict_last
    gemvT_atomic<1><<<dim3(NN / 2048, S_FULL), blk>>>(W, s1, s2, NN / S_FULL);

    // step 3: s3 = W^T s2 (full 268 MB) descending; evict_first streaming
    gemvT_atomic<2><<<dim3(NN / 2048, S_FULL), blk>>>(W, s2, s3, NN / S_FULL);

    // step 4: out[j] = W[d,d] * (W^T s3)[d] over last 256 columns, fused scale
    gemvT_lastcols_atomic<<<S_OUT, blk>>>(W, s3, out, NN / S_OUT);
}

// round 17
// speedup vs baseline: 1.4173x; 1.4173x over previous
#include <cuda_runtime.h>
#include <cuda_bf16.h>

#define NN 8192
#define IN_N 1024
#define OUT_N 256

#define S_IN   64            // row splits for input gemv (16 rows each)
#define S_FULL 128           // row splits for 8-wide full gemv (64 rows each)
#define S_OUT  256           // row splits for last-cols gemv (32 rows each)
#define TAIL_START 38        // step-2 rows >= this (of 64/split) pinned evict_last (~109 MB)

// scratch (no allocation allowed): three s vectors, zeroed each call
__device__ float g_s[3][NN];

// ---------------------------------------------------------------------------
// 32-byte (8-float) L2 eviction-priority loads. NON-volatile: pure loads,
// compiler remains free to batch/reorder them (R16's volatile form killed MLP).
// ptxas only accepts evict_* on .v8.b32/.v4.b64 vector forms.
// ---------------------------------------------------------------------------
struct f8 { float v[8]; };

__device__ __forceinline__ f8 ldg8_evict_last(const float* p) {
    unsigned long long x0, x1, x2, x3;
    asm("ld.global.nc.L2::evict_last.v4.b64 {%0,%1,%2,%3}, [%4];"
        : "=l"(x0), "=l"(x1), "=l"(x2), "=l"(x3) : "l"(p));
    f8 r;
    *reinterpret_cast<unsigned long long*>(&r.v[0]) = x0;
    *reinterpret_cast<unsigned long long*>(&r.v[2]) = x1;
    *reinterpret_cast<unsigned long long*>(&r.v[4]) = x2;
    *reinterpret_cast<unsigned long long*>(&r.v[6]) = x3;
    return r;
}
__device__ __forceinline__ f8 ldg8_evict_first(const float* p) {
    unsigned long long x0, x1, x2, x3;
    asm("ld.global.nc.L2::evict_first.v4.b64 {%0,%1,%2,%3}, [%4];"
        : "=l"(x0), "=l"(x1), "=l"(x2), "=l"(x3) : "l"(p));
    f8 r;
    *reinterpret_cast<unsigned long long*>(&r.v[0]) = x0;
    *reinterpret_cast<unsigned long long*>(&r.v[2]) = x1;
    *reinterpret_cast<unsigned long long*>(&r.v[4]) = x2;
    *reinterpret_cast<unsigned long long*>(&r.v[6]) = x3;
    return r;
}

// ---------------------------------------------------------------------------
// zero the accumulator vectors and the output
// ---------------------------------------------------------------------------
__global__ __launch_bounds__(256) void zero_accum(float* __restrict__ s,
                                                  float* __restrict__ out)
{
    const int i = blockIdx.x * blockDim.x + threadIdx.x;
    if (i < 3 * NN) s[i] = 0.f;
    if (i < OUT_N)  out[i] = 0.f;
}

// ---------------------------------------------------------------------------
// step 1 (R14-proven form): 4 cols/thread float4, ascending, plain __ldg.
// grid (NN/1024, S_IN) = (8, 64), 16 rows/split over rows 0..1023.
// ---------------------------------------------------------------------------
__global__ __launch_bounds__(256) void gemvT4_atomic(
    const float* __restrict__ W, const float* __restrict__ v,
    float* __restrict__ s_out, int rows_per_split)
{
    const int split = blockIdx.y;
    const int c4 = blockIdx.x * blockDim.x + threadIdx.x;
    const int r0 = split * rows_per_split;

    const float4* __restrict__ W4 = reinterpret_cast<const float4*>(W);

    float ax = 0.f, ay = 0.f, az = 0.f, aw = 0.f;

    for (int i = 0; i < rows_per_split; i += 4) {
#pragma unroll
        for (int u = 0; u < 4; u++) {
            const int r = r0 + i + u;
            const float sv = __ldg(&v[r]);
            const float4 w = __ldg(&W4[(size_t)r * (NN / 4) + c4]);
            ax = fmaf(w.x, sv, ax);
            ay = fmaf(w.y, sv, ay);
            az = fmaf(w.z, sv, az);
            aw = fmaf(w.w, sv, aw);
        }
    }

    float* dst = s_out + 4 * c4;
    atomicAdd(dst + 0, ax);
    atomicAdd(dst + 1, ay);
    atomicAdd(dst + 2, az);
    atomicAdd(dst + 3, aw);
}

// ---------------------------------------------------------------------------
// step 2: 8 cols/thread, ascending, evict-policy pinning.
//   rows < TAIL_START: evict_first (stream, don't displace pinned tail)
//   rows >= TAIL_START: evict_last (pin ~109 MB for step 3)
// grid (NN/2048, S_FULL) = (4, 128) = 512 blocks, 64 rows/split.
// ---------------------------------------------------------------------------
__global__ __launch_bounds__(256) void gemvT8_pin(
    const float* __restrict__ W, const float* __restrict__ v,
    float* __restrict__ s_out, int rows_per_split)
{
    const int split = blockIdx.y;
    const int c8 = blockIdx.x * blockDim.x + threadIdx.x;   // 8-col group index
    const int r0 = split * rows_per_split;

    float acc[8];
#pragma unroll
    for (int k = 0; k < 8; k++) acc[k] = 0.f;

    for (int i = 0; i < rows_per_split; i += 4) {
#pragma unroll
        for (int u = 0; u < 4; u++) {
            const int ri = i + u;
            const int r  = r0 + ri;
            const float sv = __ldg(&v[r]);
            const float* wp = W + (size_t)r * NN + 8 * c8;
            f8 w = (ri >= TAIL_START) ? ldg8_evict_last(wp)
                                      : ldg8_evict_first(wp);
#pragma unroll
            for (int k = 0; k < 8; k++)
                acc[k] = fmaf(w.v[k], sv, acc[k]);
        }
    }

    float* dst = s_out + 8 * c8;
#pragma unroll
    for (int k = 0; k < 8; k++)
        atomicAdd(dst + k, acc[k]);
}

// ---------------------------------------------------------------------------
// step 3: 8 cols/thread (2x plain __ldg float4 -> proven MLP path),
// DESCENDING rows: consumes step 2's pinned tail (L2 hits) first, then
// streams the head misses. grid (4, 128) = 512 blocks, 64 rows/split.
// ---------------------------------------------------------------------------
__global__ __launch_bounds__(256) void gemvT8_desc(
    const float* __restrict__ W, const float* __restrict__ v,
    float* __restrict__ s_out, int rows_per_split)
{
    const int split = blockIdx.y;
    const int c8 = blockIdx.x * blockDim.x + threadIdx.x;
    const int r0 = split * rows_per_split;

    const float4* __restrict__ W4 = reinterpret_cast<const float4*>(W);

    float acc[8];
#pragma unroll
    for (int k = 0; k < 8; k++) acc[k] = 0.f;

    for (int i = 0; i < rows_per_split; i += 4) {
        const int ib = rows_per_split - 4 - i;     // descending
#pragma unroll
        for (int u = 0; u < 4; u++) {
            const int r = r0 + ib + u;
            const float sv = __ldg(&v[r]);
            const float4 wa = __ldg(&W4[(size_t)r * (NN / 4) + 2 * c8 + 0]);
            const float4 wb = __ldg(&W4[(size_t)r * (NN / 4) + 2 * c8 + 1]);
            acc[0] = fmaf(wa.x, sv, acc[0]);
            acc[1] = fmaf(wa.y, sv, acc[1]);
            acc[2] = fmaf(wa.z, sv, acc[2]);
            acc[3] = fmaf(wa.w, sv, acc[3]);
            acc[4] = fmaf(wb.x, sv, acc[4]);
            acc[5] = fmaf(wb.y, sv, acc[5]);
            acc[6] = fmaf(wb.z, sv, acc[6]);
            acc[7] = fmaf(wb.w, sv, acc[7]);
        }
    }

    float* dst = s_out + 8 * c8;
#pragma unroll
    for (int k = 0; k < 8; k++)
        atomicAdd(dst + k, acc[k]);
}

// ---------------------------------------------------------------------------
// step 4: last-256-columns gemv fused with diagonal scale:
//   out[j] += W[d,d] * sum_{i in split} W[i, NN-256+j] * v[i],  d = NN-256+j
// ---------------------------------------------------------------------------
__global__ __launch_bounds__(256) void gemvT_lastcols_atomic(
    const float* __restrict__ W, const float* __restrict__ v,
    float* __restrict__ out, int rows_per_split)
{
    const int split = blockIdx.x;
    const int j = threadIdx.x;                 // 0..255
    const int colg = NN - OUT_N + j;
    const int r0 = split * rows_per_split;

    float acc = 0.f;
#pragma unroll 4
    for (int i = 0; i < rows_per_split; i++) {
        const int r = r0 + i;
        acc = fmaf(__ldg(&W[(size_t)r * NN + colg]), __ldg(&v[r]), acc);
    }

    const float wdd = __ldg(&W[(size_t)colg * NN + colg]);
    atomicAdd(&out[j], wdd * acc);
}

extern "C" void kernel_launch(void* const* d_in, const int* in_sizes, int n_in,
                              void* d_out, int out_size)
{
    // identify inputs by size (robust to ordering): x=1024, W=8192*8192
    const float* x = nullptr;
    const float* W = nullptr;
    for (int i = 0; i < n_in; i++) {
        if (in_sizes[i] == IN_N) x = (const float*)d_in[i];
        else if (in_sizes[i] == NN * NN) W = (const float*)d_in[i];
    }
    if (!x) x = (const float*)d_in[0];
    if (!W) W = (const float*)d_in[1];
    float* out = (float*)d_out;

    float* sbase; cudaGetSymbolAddress((void**)&sbase, g_s);
    float* s1 = sbase;            // g_s[0]
    float* s2 = sbase + NN;       // g_s[1]
    float* s3 = sbase + 2 * NN;   // g_s[2]

    const dim3 blk(256);

    // zero accumulators + out (must precede all atomics; stream serializes)
    zero_accum<<<(3 * NN + 255) / 256, blk>>>(sbase, out);

    // step 1: s1 = W[0:1024,:]^T x  (32 MB; lands in L2, re-read by step 2)
    gemvT4_atomic<<<dim3(NN / 1024, S_IN), blk>>>(W, x, s1, IN_N / S_IN);

    // step 2: s2 = W^T s1 (268 MB) ascending; tail rows pinned evict_last
    gemvT8_pin<<<dim3(NN / 2048, S_FULL), blk>>>(W, s1, s2, NN / S_FULL);

    // step 3: s3 = W^T s2 (268 MB) descending; consumes pinned tail first
    gemvT8_desc<<<dim3(NN / 2048, S_FULL), blk>>>(W, s2, s3, NN / S_FULL);

    // step 4: out[j] = W[d,d] * (W^T s3)[d] over last 256 columns, fused scale
    gemvT_lastcols_atomic<<<S_OUT, blk>>>(W, s3, out, NN / S_OUT);
}